// round 1
// baseline (speedup 1.0000x reference)
#include <cuda_runtime.h>
#include <cuda_bf16.h>
#include <cfloat>

// Problem constants
#define B_  4
#define L_  1024
#define D_  1024
#define H_  16
#define HB_ 64   // H*B

// ---------------------------------------------------------------------------
// Scratch (static __device__ arrays; no allocation allowed)
// q,q2,k,v stored as [H,B,L,64]  (z = h*B + b)
// ---------------------------------------------------------------------------
__device__ float g_q  [HB_ * L_ * 64];
__device__ float g_q2 [HB_ * L_ * 64];
__device__ float g_k  [HB_ * L_ * 64];
__device__ float g_v  [HB_ * L_ * 64];
__device__ float g_att[B_ * L_ * D_];
__device__ float g_x  [B_ * L_ * D_];
__device__ float g_pfb[HB_ * L_ * L_];   // fallback p buffer if out_size is small

// ---------------------------------------------------------------------------
// Generic fp32 GEMM: C[M,N] = A[M,K] @ W[K,N]
// BM=BN=128, BK=8, 256 threads, 8x8 micro-tile.
// mode 0: scatter output to [H,B,L,64] layout (projections, N must be 1024)
// mode 1: C[m,n] = acc + R[m,n]   (Wo GEMM with fused residual)
// ---------------------------------------------------------------------------
__global__ __launch_bounds__(256)
void gemm128(const float* __restrict__ A, const float* __restrict__ W,
             float* __restrict__ C, const float* __restrict__ R,
             int K, int N, int mode)
{
    __shared__ float As[8][132];
    __shared__ float Bs[8][132];
    const int tid = threadIdx.x;
    const int m0 = blockIdx.y * 128;
    const int n0 = blockIdx.x * 128;
    const int a_row = tid >> 1, a_col = (tid & 1) * 4;
    const int b_row = tid >> 5, b_col = (tid & 31) * 4;
    const int ty = tid >> 4, tx = tid & 15;
    float acc[8][8] = {};

    for (int k0 = 0; k0 < K; k0 += 8) {
        float4 av = *(const float4*)&A[(size_t)(m0 + a_row) * K + k0 + a_col];
        As[a_col + 0][a_row] = av.x;
        As[a_col + 1][a_row] = av.y;
        As[a_col + 2][a_row] = av.z;
        As[a_col + 3][a_row] = av.w;
        *(float4*)&Bs[b_row][b_col] =
            *(const float4*)&W[(size_t)(k0 + b_row) * N + n0 + b_col];
        __syncthreads();
        #pragma unroll
        for (int kk = 0; kk < 8; kk++) {
            float ar[8], br[8];
            *(float4*)&ar[0] = *(const float4*)&As[kk][ty * 8];
            *(float4*)&ar[4] = *(const float4*)&As[kk][ty * 8 + 4];
            *(float4*)&br[0] = *(const float4*)&Bs[kk][tx * 8];
            *(float4*)&br[4] = *(const float4*)&Bs[kk][tx * 8 + 4];
            #pragma unroll
            for (int i = 0; i < 8; i++)
                #pragma unroll
                for (int j = 0; j < 8; j++)
                    acc[i][j] = fmaf(ar[i], br[j], acc[i][j]);
        }
        __syncthreads();
    }

    #pragma unroll
    for (int i = 0; i < 8; i++) {
        const int m = m0 + ty * 8 + i;
        #pragma unroll
        for (int j = 0; j < 8; j++) {
            const int n = n0 + tx * 8 + j;
            if (mode == 0) {
                const int h = n >> 6, d = n & 63;
                const int b = m >> 10, l = m & 1023;
                C[(size_t)((h * B_ + b) * L_ + l) * 64 + d] = acc[i][j];
            } else {
                const size_t idx = (size_t)m * N + n;
                C[idx] = acc[i][j] + R[idx];
            }
        }
    }
}

// ---------------------------------------------------------------------------
// Score kernel: S[i,j] = (q_i.k_j + q2_i.Er[h, L-1-(i-j)]) / 8  for j <= i.
// 64x64 tiles, lower triangle only. Writes raw logits into p buffer.
// The skew is folded into the Er band index: band row t = 63 + (j - i) within
// a tile whose lowest Er row is rbase = L-64-i0+j0.
// ---------------------------------------------------------------------------
__global__ __launch_bounds__(256)
void score_kernel(const float* __restrict__ q, const float* __restrict__ q2,
                  const float* __restrict__ k, const float* __restrict__ Er,
                  float* __restrict__ p)
{
    const int tj = blockIdx.x, ti = blockIdx.y, z = blockIdx.z;
    if (tj > ti) return;
    const int i0 = ti * 64, j0 = tj * 64;
    const int h = z >> 2;                 // z = h*B + b
    const int rbase = L_ - 64 - i0 + j0;  // >= 0 always

    __shared__ float qs [16][68];
    __shared__ float q2s[16][68];
    __shared__ float ks [16][68];
    __shared__ float ers[16][132];        // [d_local][band_t], t in [0,127)

    const float* qb  = q  + (size_t)z * L_ * 64;
    const float* q2b = q2 + (size_t)z * L_ * 64;
    const float* kb  = k  + (size_t)z * L_ * 64;
    const float* erh = Er + (size_t)h * L_ * 64;

    const int tid  = threadIdx.x;
    const int ty   = tid >> 4, tx = tid & 15;
    const int lrow = tid >> 2, lcg = (tid & 3) * 4;
    const int erow = tid >> 1, ecg = (tid & 1) * 8;
    float acc[4][4] = {};

    for (int dk0 = 0; dk0 < 64; dk0 += 16) {
        float4 a;
        a = *(const float4*)&qb[(size_t)(i0 + lrow) * 64 + dk0 + lcg];
        qs[lcg+0][lrow] = a.x; qs[lcg+1][lrow] = a.y;
        qs[lcg+2][lrow] = a.z; qs[lcg+3][lrow] = a.w;
        a = *(const float4*)&q2b[(size_t)(i0 + lrow) * 64 + dk0 + lcg];
        q2s[lcg+0][lrow] = a.x; q2s[lcg+1][lrow] = a.y;
        q2s[lcg+2][lrow] = a.z; q2s[lcg+3][lrow] = a.w;
        a = *(const float4*)&kb[(size_t)(j0 + lrow) * 64 + dk0 + lcg];
        ks[lcg+0][lrow] = a.x; ks[lcg+1][lrow] = a.y;
        ks[lcg+2][lrow] = a.z; ks[lcg+3][lrow] = a.w;
        {
            const int r = rbase + erow;
            const bool ok = (erow < 127) && (r < L_);  // OOB rows only feed masked j>i
            #pragma unroll
            for (int cc = 0; cc < 8; cc += 4) {
                float4 e = ok ? *(const float4*)&erh[(size_t)r * 64 + dk0 + ecg + cc]
                              : make_float4(0.f, 0.f, 0.f, 0.f);
                ers[ecg + cc + 0][erow] = e.x;
                ers[ecg + cc + 1][erow] = e.y;
                ers[ecg + cc + 2][erow] = e.z;
                ers[ecg + cc + 3][erow] = e.w;
            }
        }
        __syncthreads();

        const int ebase = 60 + 4 * (tx - ty);   // t = 63 + (j-i), minus 3 for jj-ii offset
        #pragma unroll
        for (int kk = 0; kk < 16; kk++) {
            float qa[4], ka[4], q2a[4], er7[7];
            *(float4*)qa  = *(const float4*)&qs [kk][ty * 4];
            *(float4*)q2a = *(const float4*)&q2s[kk][ty * 4];
            *(float4*)ka  = *(const float4*)&ks [kk][tx * 4];
            #pragma unroll
            for (int m2 = 0; m2 < 7; m2++) er7[m2] = ers[kk][ebase + m2];
            #pragma unroll
            for (int ii = 0; ii < 4; ii++)
                #pragma unroll
                for (int jj = 0; jj < 4; jj++)
                    acc[ii][jj] += qa[ii] * ka[jj] + q2a[ii] * er7[3 + jj - ii];
        }
        __syncthreads();
    }

    #pragma unroll
    for (int ii = 0; ii < 4; ii++) {
        const int i = i0 + ty * 4 + ii;
        #pragma unroll
        for (int jj = 0; jj < 4; jj++) {
            const int j = j0 + tx * 4 + jj;
            p[((size_t)z * L_ + i) * L_ + j] = acc[ii][jj] * 0.125f;  // /TEMP
        }
    }
}

// ---------------------------------------------------------------------------
// Row softmax in place over j in [0, i]; writes 0 for j > i (also covers
// the never-written upper-triangle tiles and the poisoned output buffer).
// ---------------------------------------------------------------------------
__global__ __launch_bounds__(256)
void softmax_kernel(float* __restrict__ p)
{
    const int i = blockIdx.x, z = blockIdx.y, tid = threadIdx.x;
    float* row = p + ((size_t)z * L_ + i) * L_;
    const int n = i + 1;
    __shared__ float sh[8];

    float m = -FLT_MAX;
    for (int j = tid; j < n; j += 256) m = fmaxf(m, row[j]);
    #pragma unroll
    for (int o = 16; o > 0; o >>= 1) m = fmaxf(m, __shfl_xor_sync(0xffffffffu, m, o));
    if ((tid & 31) == 0) sh[tid >> 5] = m;
    __syncthreads();
    float mt = -FLT_MAX;
    #pragma unroll
    for (int w = 0; w < 8; w++) mt = fmaxf(mt, sh[w]);
    __syncthreads();

    float s = 0.f;
    for (int j = tid; j < n; j += 256) s += __expf(row[j] - mt);
    #pragma unroll
    for (int o = 16; o > 0; o >>= 1) s += __shfl_xor_sync(0xffffffffu, s, o);
    if ((tid & 31) == 0) sh[tid >> 5] = s;
    __syncthreads();
    float stot = 0.f;
    #pragma unroll
    for (int w = 0; w < 8; w++) stot += sh[w];
    const float inv = 1.0f / stot;

    for (int j = tid; j < n; j += 256) row[j] = __expf(row[j] - mt) * inv;
    for (int j = n + tid; j < L_; j += 256) row[j] = 0.f;
}

// ---------------------------------------------------------------------------
// out[z, i, :] = sum_{j<=i} p[z,i,j] * v[z,j,:]  -> written as [B, L, H*64]
// p already has exact zeros for j > i, so the diagonal K-chunk needs no mask.
// ---------------------------------------------------------------------------
__global__ __launch_bounds__(256)
void pv_kernel(const float* __restrict__ p, const float* __restrict__ v,
               float* __restrict__ att)
{
    const int it = blockIdx.x, z = blockIdx.y;
    const int i0 = it * 64;
    const int h = z >> 2, b = z & 3;
    __shared__ float ps[16][68];
    __shared__ float vs[16][68];
    const int tid  = threadIdx.x;
    const int ty   = tid >> 4, tx = tid & 15;
    const int lrow = tid >> 2, lcg = (tid & 3) * 4;
    const int vrow = tid >> 4, vcg = (tid & 15) * 4;
    float acc[4][4] = {};

    const int kend = i0 + 64;
    for (int kj = 0; kj < kend; kj += 16) {
        float4 pr = *(const float4*)&p[((size_t)z * L_ + i0 + lrow) * L_ + kj + lcg];
        ps[lcg+0][lrow] = pr.x; ps[lcg+1][lrow] = pr.y;
        ps[lcg+2][lrow] = pr.z; ps[lcg+3][lrow] = pr.w;
        *(float4*)&vs[vrow][vcg] =
            *(const float4*)&v[((size_t)z * L_ + kj + vrow) * 64 + vcg];
        __syncthreads();
        #pragma unroll
        for (int kk = 0; kk < 16; kk++) {
            float pa[4], va[4];
            *(float4*)pa = *(const float4*)&ps[kk][ty * 4];
            *(float4*)va = *(const float4*)&vs[kk][tx * 4];
            #pragma unroll
            for (int ii = 0; ii < 4; ii++)
                #pragma unroll
                for (int jj = 0; jj < 4; jj++)
                    acc[ii][jj] += pa[ii] * va[jj];
        }
        __syncthreads();
    }

    #pragma unroll
    for (int ii = 0; ii < 4; ii++)
        #pragma unroll
        for (int jj = 0; jj < 4; jj++)
            att[(size_t)(b * L_ + i0 + ty * 4 + ii) * D_ + h * 64 + tx * 4 + jj]
                = acc[ii][jj];
}

// ---------------------------------------------------------------------------
// LayerNorm: y = (x - mu) * rsqrt(var + eps) * g + b, per row of 1024.
// ---------------------------------------------------------------------------
__global__ __launch_bounds__(256)
void ln_kernel(const float* __restrict__ x, const float* __restrict__ gam,
               const float* __restrict__ bet, float* __restrict__ y)
{
    const int r = blockIdx.x, tid = threadIdx.x;
    __shared__ float sh[16];
    const float* xr = x + (size_t)r * D_;
    float4 xv = *(const float4*)&xr[tid * 4];
    float s  = xv.x + xv.y + xv.z + xv.w;
    float ss = xv.x*xv.x + xv.y*xv.y + xv.z*xv.z + xv.w*xv.w;
    #pragma unroll
    for (int o = 16; o > 0; o >>= 1) {
        s  += __shfl_xor_sync(0xffffffffu, s,  o);
        ss += __shfl_xor_sync(0xffffffffu, ss, o);
    }
    if ((tid & 31) == 0) { sh[tid >> 5] = s; sh[8 + (tid >> 5)] = ss; }
    __syncthreads();
    float st = 0.f, sst = 0.f;
    #pragma unroll
    for (int w = 0; w < 8; w++) { st += sh[w]; sst += sh[8 + w]; }
    const float mu  = st * (1.0f / D_);
    const float var = sst * (1.0f / D_) - mu * mu;
    const float rs  = rsqrtf(var + 1e-5f);
    float4 gv = *(const float4*)&gam[tid * 4];
    float4 bv = *(const float4*)&bet[tid * 4];
    float4 o4;
    o4.x = (xv.x - mu) * rs * gv.x + bv.x;
    o4.y = (xv.y - mu) * rs * gv.y + bv.y;
    o4.z = (xv.z - mu) * rs * gv.z + bv.z;
    o4.w = (xv.w - mu) * rs * gv.w + bv.w;
    *(float4*)&y[(size_t)r * D_ + tid * 4] = o4;
}

// ---------------------------------------------------------------------------
// Launch. Inputs (metadata order): q_in k_in v_in Wq Wq2 Wk Wv Wo ln_g ln_b Er mask
// Output: y [B,L,D] followed by p [H,B,L,L].
// ---------------------------------------------------------------------------
extern "C" void kernel_launch(void* const* d_in, const int* in_sizes, int n_in,
                              void* d_out, int out_size)
{
    const float* q_in = (const float*)d_in[0];
    const float* k_in = (const float*)d_in[1];
    const float* v_in = (const float*)d_in[2];
    const float* Wq   = (const float*)d_in[3];
    const float* Wq2  = (const float*)d_in[4];
    const float* Wk   = (const float*)d_in[5];
    const float* Wv   = (const float*)d_in[6];
    const float* Wo   = (const float*)d_in[7];
    const float* ln_g = (const float*)d_in[8];
    const float* ln_b = (const float*)d_in[9];
    const float* Er   = (const float*)d_in[10];
    (void)in_sizes; (void)n_in;

    float *pq, *pq2, *pk, *pvv, *patt, *px, *pfb;
    cudaGetSymbolAddress((void**)&pq,   g_q);
    cudaGetSymbolAddress((void**)&pq2,  g_q2);
    cudaGetSymbolAddress((void**)&pk,   g_k);
    cudaGetSymbolAddress((void**)&pvv,  g_v);
    cudaGetSymbolAddress((void**)&patt, g_att);
    cudaGetSymbolAddress((void**)&px,   g_x);
    cudaGetSymbolAddress((void**)&pfb,  g_pfb);

    float* y_out = (float*)d_out;
    const long long ysz = (long long)B_ * L_ * D_;          // 4,194,304
    const long long psz = (long long)HB_ * L_ * L_;         // 67,108,864
    float* p_buf = ((long long)out_size >= ysz + psz) ? (y_out + ysz) : pfb;

    const dim3 gproj(8, 32);   // N/128, M/128 for 4096x1024 GEMMs
    gemm128<<<gproj, 256>>>(q_in, Wq,  pq,  nullptr, D_, H_ * 64, 0);
    gemm128<<<gproj, 256>>>(q_in, Wq2, pq2, nullptr, D_, H_ * 64, 0);
    gemm128<<<gproj, 256>>>(k_in, Wk,  pk,  nullptr, D_, H_ * 64, 0);
    gemm128<<<gproj, 256>>>(v_in, Wv,  pvv, nullptr, D_, H_ * 64, 0);

    score_kernel<<<dim3(16, 16, HB_), 256>>>(pq, pq2, pk, Er, p_buf);
    softmax_kernel<<<dim3(L_, HB_), 256>>>(p_buf);
    pv_kernel<<<dim3(16, HB_), 256>>>(p_buf, pvv, patt);

    gemm128<<<gproj, 256>>>(patt, Wo, px, q_in, D_, D_, 1);
    ln_kernel<<<B_ * L_, 256>>>(px, ln_g, ln_b, y_out);
}

// round 3
// speedup vs baseline: 1.5980x; 1.5980x over previous
#include <cuda_runtime.h>
#include <cuda_bf16.h>
#include <cfloat>
#include <cstdint>

// Problem constants
#define B_  4
#define L_  1024
#define D_  1024
#define H_  16
#define HB_ 64   // H*B

// ===========================================================================
// Scratch (static __device__)
// Activations & attention buffers: [B*L, 1024] row-major (n = h*64 + d)
// ===========================================================================
__device__ float g_q  [B_ * L_ * D_];
__device__ float g_q2 [B_ * L_ * D_];
__device__ float g_k  [B_ * L_ * D_];
__device__ float g_v  [B_ * L_ * D_];
__device__ float g_att[B_ * L_ * D_];
__device__ float g_x  [B_ * L_ * D_];
__device__ float g_pfb[HB_ * L_ * L_];               // fallback p buffer
__device__ __nv_bfloat16 g_ah[B_ * L_ * D_];         // activation split hi
__device__ __nv_bfloat16 g_al[B_ * L_ * D_];         // activation split lo
__device__ __nv_bfloat16 g_wh[D_ * D_];              // weight^T split hi [N,K]
__device__ __nv_bfloat16 g_wl[D_ * D_];              // weight^T split lo [N,K]

// ===========================================================================
// Small PTX helpers (all legal on base sm_103 target)
// ===========================================================================
__device__ __forceinline__ uint32_t smem_u32(const void* p) {
    uint32_t a;
    asm("{ .reg .u64 t; cvta.to.shared.u64 t, %1; cvt.u32.u64 %0, t; }"
        : "=r"(a) : "l"(p));
    return a;
}
__device__ __forceinline__ void cpa16(uint32_t saddr, const void* g) {
    asm volatile("cp.async.cg.shared.global [%0], [%1], 16;" :: "r"(saddr), "l"(g));
}
__device__ __forceinline__ void ldsm_x4(uint32_t* r, uint32_t addr) {
    asm volatile("ldmatrix.sync.aligned.m8n8.x4.shared.b16 {%0,%1,%2,%3}, [%4];"
                 : "=r"(r[0]), "=r"(r[1]), "=r"(r[2]), "=r"(r[3]) : "r"(addr));
}
__device__ __forceinline__ void mma16816(float* c, const uint32_t* a, const uint32_t* b) {
    asm volatile(
        "mma.sync.aligned.m16n8k16.row.col.f32.bf16.bf16.f32 "
        "{%0,%1,%2,%3}, {%4,%5,%6,%7}, {%8,%9}, {%0,%1,%2,%3};"
        : "+f"(c[0]), "+f"(c[1]), "+f"(c[2]), "+f"(c[3])
        : "r"(a[0]), "r"(a[1]), "r"(a[2]), "r"(a[3]), "r"(b[0]), "r"(b[1]));
}

// ===========================================================================
// fp32 -> bf16 hi/lo split (elementwise, n multiple of 4)
// ===========================================================================
__global__ __launch_bounds__(256)
void split_act(const float* __restrict__ x, __nv_bfloat16* __restrict__ hi,
               __nv_bfloat16* __restrict__ lo, int n)
{
    int i = (blockIdx.x * 256 + threadIdx.x) * 4;
    if (i >= n) return;
    float4 v = *(const float4*)&x[i];
    __nv_bfloat16 h0 = __float2bfloat16(v.x);
    __nv_bfloat16 h1 = __float2bfloat16(v.y);
    __nv_bfloat16 h2 = __float2bfloat16(v.z);
    __nv_bfloat16 h3 = __float2bfloat16(v.w);
    __nv_bfloat162 hp0; hp0.x = h0; hp0.y = h1;
    __nv_bfloat162 hp1; hp1.x = h2; hp1.y = h3;
    *(__nv_bfloat162*)&hi[i]     = hp0;
    *(__nv_bfloat162*)&hi[i + 2] = hp1;
    __nv_bfloat162 lp0, lp1;
    lp0.x = __float2bfloat16(v.x - __bfloat162float(h0));
    lp0.y = __float2bfloat16(v.y - __bfloat162float(h1));
    lp1.x = __float2bfloat16(v.z - __bfloat162float(h2));
    lp1.y = __float2bfloat16(v.w - __bfloat162float(h3));
    *(__nv_bfloat162*)&lo[i]     = lp0;
    *(__nv_bfloat162*)&lo[i + 2] = lp1;
}

// W[K,N] fp32 -> Wt[N,K] bf16 hi/lo (transpose + split), 32x32 tiles
__global__ __launch_bounds__(256)
void split_w_t(const float* __restrict__ W, __nv_bfloat16* __restrict__ th,
               __nv_bfloat16* __restrict__ tl, int Kd, int Nd)
{
    __shared__ float t[32][33];
    const int bx = blockIdx.x * 32;   // over N
    const int by = blockIdx.y * 32;   // over K
    const int tx = threadIdx.x & 31;
    const int ty = threadIdx.x >> 5;  // 0..7
    #pragma unroll
    for (int r = ty; r < 32; r += 8)
        t[r][tx] = W[(size_t)(by + r) * Nd + bx + tx];
    __syncthreads();
    #pragma unroll
    for (int r = ty; r < 32; r += 8) {
        float v = t[tx][r];           // = W[by+tx][bx+r]
        __nv_bfloat16 h = __float2bfloat16(v);
        th[(size_t)(bx + r) * Kd + by + tx] = h;
        tl[(size_t)(bx + r) * Kd + by + tx] = __float2bfloat16(v - __bfloat162float(h));
    }
}

// ===========================================================================
// HMMA split-bf16 GEMM: C[M,N] = (Ah+Al)[M,K] @ (Bh+Bl)[N,K]^T (+ R)
// CTA tile 128x128, K-chunk 32, 256 threads (8 warps of 32x64),
// double-buffered cp.async. Smem rows padded to 40 bf16 (80 B).
// ===========================================================================
#define TSTRIDE 40                       // bf16 elems per smem row
#define TILE_BYTES (128 * TSTRIDE * 2)   // 10240 bytes per tile
#define STAGE_BYTES (4 * TILE_BYTES)     // Ah, Al, Bh, Bl

__global__ __launch_bounds__(256)
void gemm_tc(const __nv_bfloat16* __restrict__ Ah, const __nv_bfloat16* __restrict__ Al,
             const __nv_bfloat16* __restrict__ Bh, const __nv_bfloat16* __restrict__ Bl,
             float* __restrict__ C, const float* __restrict__ R, int K, int N)
{
    extern __shared__ __align__(16) char smem[];
    const uint32_t sb0 = smem_u32(smem);
    const int tid  = threadIdx.x;
    const int wid  = tid >> 5;
    const int lane = tid & 31;
    const int m0 = blockIdx.y * 128;
    const int n0 = blockIdx.x * 128;
    const int wm = (wid & 3) * 32;    // warp M offset in tile
    const int wn = (wid >> 2) * 64;   // warp N offset in tile

    const __nv_bfloat16* gT[4] = {
        Ah + (size_t)m0 * K, Al + (size_t)m0 * K,
        Bh + (size_t)n0 * K, Bl + (size_t)n0 * K };

    // cp.async one K-chunk (all 4 tiles: 128 rows x 32 bf16 each)
    auto load_chunk = [&](int c, int st) {
        const uint32_t sb = sb0 + st * STAGE_BYTES;
        const int k0 = c * 32;
        #pragma unroll
        for (int t = 0; t < 4; t++) {
            const __nv_bfloat16* g = gT[t] + k0;
            const uint32_t tb = sb + t * TILE_BYTES;
            #pragma unroll
            for (int it = 0; it < 2; it++) {
                int o   = tid + it * 256;      // 0..511
                int row = o >> 2, c16 = o & 3; // 4 x 16B per row
                cpa16(tb + row * (TSTRIDE * 2) + c16 * 16,
                      g + (size_t)row * K + c16 * 8);
            }
        }
        asm volatile("cp.async.commit_group;" ::: "memory");
    };

    float acc[2][8][4];
    #pragma unroll
    for (int i = 0; i < 2; i++)
        #pragma unroll
        for (int j = 0; j < 8; j++)
            #pragma unroll
            for (int q = 0; q < 4; q++) acc[i][j][q] = 0.f;

    // ldmatrix lane addressing (within a warp)
    const int arow = lane & 15;                  // A: rows of the two 8x8 halves
    const int acolq = (lane >> 4) * 8;           // A: k-half select
    const int nrow = ((lane >> 4) * 8) + (lane & 7);   // B: n row
    const int bcolq = ((lane >> 3) & 1) * 8;     // B: k-half select

    const int NC = K / 32;
    load_chunk(0, 0);

    for (int c = 0; c < NC; ++c) {
        const int st = c & 1;
        if (c + 1 < NC) {
            load_chunk(c + 1, st ^ 1);
            asm volatile("cp.async.wait_group 1;" ::: "memory");
        } else {
            asm volatile("cp.async.wait_group 0;" ::: "memory");
        }
        __syncthreads();

        const uint32_t sb  = sb0 + st * STAGE_BYTES;
        const uint32_t sAh = sb;
        const uint32_t sAl = sb + TILE_BYTES;
        const uint32_t sBh = sb + 2 * TILE_BYTES;
        const uint32_t sBl = sb + 3 * TILE_BYTES;

        #pragma unroll
        for (int k16 = 0; k16 < 32; k16 += 16) {
            uint32_t ah[2][4], al[2][4], bh[4][4], bl[4][4];
            #pragma unroll
            for (int mt = 0; mt < 2; mt++) {
                uint32_t off = ((wm + mt * 16 + arow) * TSTRIDE + k16 + acolq) * 2;
                ldsm_x4(ah[mt], sAh + off);
                ldsm_x4(al[mt], sAl + off);
            }
            #pragma unroll
            for (int p = 0; p < 4; p++) {
                uint32_t off = ((wn + p * 16 + nrow) * TSTRIDE + k16 + bcolq) * 2;
                ldsm_x4(bh[p], sBh + off);
                ldsm_x4(bl[p], sBl + off);
            }
            #pragma unroll
            for (int mt = 0; mt < 2; mt++)
                #pragma unroll
                for (int nt = 0; nt < 8; nt++) {
                    const uint32_t* bhf = &bh[nt >> 1][(nt & 1) * 2];
                    const uint32_t* blf = &bl[nt >> 1][(nt & 1) * 2];
                    mma16816(acc[mt][nt], ah[mt], bhf);
                    mma16816(acc[mt][nt], ah[mt], blf);
                    mma16816(acc[mt][nt], al[mt], bhf);
                }
        }
        __syncthreads();
    }

    // Epilogue: fragment layout c0,c1 -> (m, n..n+1); c2,c3 -> (m+8, n..n+1)
    #pragma unroll
    for (int mt = 0; mt < 2; mt++) {
        const int m = m0 + wm + mt * 16 + (lane >> 2);
        #pragma unroll
        for (int nt = 0; nt < 8; nt++) {
            const int n = n0 + wn + nt * 8 + (lane & 3) * 2;
            float* cp0 = &C[(size_t)m * N + n];
            float* cp1 = &C[(size_t)(m + 8) * N + n];
            float2 o0 = make_float2(acc[mt][nt][0], acc[mt][nt][1]);
            float2 o1 = make_float2(acc[mt][nt][2], acc[mt][nt][3]);
            if (R) {
                const float2 r0 = *(const float2*)&R[(size_t)m * N + n];
                const float2 r1 = *(const float2*)&R[(size_t)(m + 8) * N + n];
                o0.x += r0.x; o0.y += r0.y;
                o1.x += r1.x; o1.y += r1.y;
            }
            *(float2*)cp0 = o0;
            *(float2*)cp1 = o1;
        }
    }
}

// ===========================================================================
// Score kernel: S[i,j] = (q_i.k_j + q2_i.Er[h, L-1-(i-j)]) / 8 for j <= i.
// q/q2/k are [B*L, 1024] with head offset h*64.
// ===========================================================================
__global__ __launch_bounds__(256)
void score_kernel(const float* __restrict__ q, const float* __restrict__ q2,
                  const float* __restrict__ k, const float* __restrict__ Er,
                  float* __restrict__ p)
{
    const int tj = blockIdx.x, ti = blockIdx.y, z = blockIdx.z;
    if (tj > ti) return;
    const int i0 = ti * 64, j0 = tj * 64;
    const int h = z >> 2, b = z & 3;
    const int rbase = L_ - 64 - i0 + j0;

    __shared__ float qs [16][68];
    __shared__ float q2s[16][68];
    __shared__ float ks [16][68];
    __shared__ float ers[16][132];

    const float* qb  = q  + (size_t)b * L_ * D_ + h * 64;
    const float* q2b = q2 + (size_t)b * L_ * D_ + h * 64;
    const float* kb  = k  + (size_t)b * L_ * D_ + h * 64;
    const float* erh = Er + (size_t)h * L_ * 64;

    const int tid  = threadIdx.x;
    const int ty   = tid >> 4, tx = tid & 15;
    const int lrow = tid >> 2, lcg = (tid & 3) * 4;
    const int erow = tid >> 1, ecg = (tid & 1) * 8;
    float acc[4][4] = {};

    for (int dk0 = 0; dk0 < 64; dk0 += 16) {
        float4 a;
        a = *(const float4*)&qb[(size_t)(i0 + lrow) * D_ + dk0 + lcg];
        qs[lcg+0][lrow] = a.x; qs[lcg+1][lrow] = a.y;
        qs[lcg+2][lrow] = a.z; qs[lcg+3][lrow] = a.w;
        a = *(const float4*)&q2b[(size_t)(i0 + lrow) * D_ + dk0 + lcg];
        q2s[lcg+0][lrow] = a.x; q2s[lcg+1][lrow] = a.y;
        q2s[lcg+2][lrow] = a.z; q2s[lcg+3][lrow] = a.w;
        a = *(const float4*)&kb[(size_t)(j0 + lrow) * D_ + dk0 + lcg];
        ks[lcg+0][lrow] = a.x; ks[lcg+1][lrow] = a.y;
        ks[lcg+2][lrow] = a.z; ks[lcg+3][lrow] = a.w;
        {
            const int r = rbase + erow;
            const bool ok = (erow < 127) && (r < L_);
            #pragma unroll
            for (int cc = 0; cc < 8; cc += 4) {
                float4 e = ok ? *(const float4*)&erh[(size_t)r * 64 + dk0 + ecg + cc]
                              : make_float4(0.f, 0.f, 0.f, 0.f);
                ers[ecg + cc + 0][erow] = e.x;
                ers[ecg + cc + 1][erow] = e.y;
                ers[ecg + cc + 2][erow] = e.z;
                ers[ecg + cc + 3][erow] = e.w;
            }
        }
        __syncthreads();

        const int ebase = 60 + 4 * (tx - ty);
        #pragma unroll
        for (int kk = 0; kk < 16; kk++) {
            float qa[4], ka[4], q2a[4], er7[7];
            *(float4*)qa  = *(const float4*)&qs [kk][ty * 4];
            *(float4*)q2a = *(const float4*)&q2s[kk][ty * 4];
            *(float4*)ka  = *(const float4*)&ks [kk][tx * 4];
            #pragma unroll
            for (int m2 = 0; m2 < 7; m2++) er7[m2] = ers[kk][ebase + m2];
            #pragma unroll
            for (int ii = 0; ii < 4; ii++)
                #pragma unroll
                for (int jj = 0; jj < 4; jj++)
                    acc[ii][jj] += qa[ii] * ka[jj] + q2a[ii] * er7[3 + jj - ii];
        }
        __syncthreads();
    }

    #pragma unroll
    for (int ii = 0; ii < 4; ii++) {
        const int i = i0 + ty * 4 + ii;
        #pragma unroll
        for (int jj = 0; jj < 4; jj++) {
            const int j = j0 + tx * 4 + jj;
            p[((size_t)z * L_ + i) * L_ + j] = acc[ii][jj] * 0.125f;
        }
    }
}

// ===========================================================================
// Row softmax in place; zeros for j > i.
// ===========================================================================
__global__ __launch_bounds__(256)
void softmax_kernel(float* __restrict__ p)
{
    const int i = blockIdx.x, z = blockIdx.y, tid = threadIdx.x;
    float* row = p + ((size_t)z * L_ + i) * L_;
    const int n = i + 1;
    __shared__ float sh[8];

    float m = -FLT_MAX;
    for (int j = tid; j < n; j += 256) m = fmaxf(m, row[j]);
    #pragma unroll
    for (int o = 16; o > 0; o >>= 1) m = fmaxf(m, __shfl_xor_sync(0xffffffffu, m, o));
    if ((tid & 31) == 0) sh[tid >> 5] = m;
    __syncthreads();
    float mt = -FLT_MAX;
    #pragma unroll
    for (int w = 0; w < 8; w++) mt = fmaxf(mt, sh[w]);
    __syncthreads();

    float s = 0.f;
    for (int j = tid; j < n; j += 256) s += __expf(row[j] - mt);
    #pragma unroll
    for (int o = 16; o > 0; o >>= 1) s += __shfl_xor_sync(0xffffffffu, s, o);
    if ((tid & 31) == 0) sh[tid >> 5] = s;
    __syncthreads();
    float stot = 0.f;
    #pragma unroll
    for (int w = 0; w < 8; w++) stot += sh[w];
    const float inv = 1.0f / stot;

    for (int j = tid; j < n; j += 256) row[j] = __expf(row[j] - mt) * inv;
    for (int j = n + tid; j < L_; j += 256) row[j] = 0.f;
}

// ===========================================================================
// pv: out[b*L+i, h*64+d] = sum_{j<=i} p[z,i,j] * v[b*L+j, h*64+d]
// ===========================================================================
__global__ __launch_bounds__(256)
void pv_kernel(const float* __restrict__ p, const float* __restrict__ v,
               float* __restrict__ att)
{
    const int it = blockIdx.x, z = blockIdx.y;
    const int i0 = it * 64;
    const int h = z >> 2, b = z & 3;
    __shared__ float ps[16][68];
    __shared__ float vs[16][68];
    const int tid  = threadIdx.x;
    const int ty   = tid >> 4, tx = tid & 15;
    const int lrow = tid >> 2, lcg = (tid & 3) * 4;
    const int vrow = tid >> 4, vcg = (tid & 15) * 4;
    float acc[4][4] = {};

    const float* vb = v + (size_t)b * L_ * D_ + h * 64;
    const int kend = i0 + 64;
    for (int kj = 0; kj < kend; kj += 16) {
        float4 pr = *(const float4*)&p[((size_t)z * L_ + i0 + lrow) * L_ + kj + lcg];
        ps[lcg+0][lrow] = pr.x; ps[lcg+1][lrow] = pr.y;
        ps[lcg+2][lrow] = pr.z; ps[lcg+3][lrow] = pr.w;
        *(float4*)&vs[vrow][vcg] =
            *(const float4*)&vb[(size_t)(kj + vrow) * D_ + vcg];
        __syncthreads();
        #pragma unroll
        for (int kk = 0; kk < 16; kk++) {
            float pa[4], va[4];
            *(float4*)pa = *(const float4*)&ps[kk][ty * 4];
            *(float4*)va = *(const float4*)&vs[kk][tx * 4];
            #pragma unroll
            for (int ii = 0; ii < 4; ii++)
                #pragma unroll
                for (int jj = 0; jj < 4; jj++)
                    acc[ii][jj] += pa[ii] * va[jj];
        }
        __syncthreads();
    }

    #pragma unroll
    for (int ii = 0; ii < 4; ii++)
        #pragma unroll
        for (int jj = 0; jj < 4; jj++)
            att[(size_t)(b * L_ + i0 + ty * 4 + ii) * D_ + h * 64 + tx * 4 + jj]
                = acc[ii][jj];
}

// ===========================================================================
// LayerNorm
// ===========================================================================
__global__ __launch_bounds__(256)
void ln_kernel(const float* __restrict__ x, const float* __restrict__ gam,
               const float* __restrict__ bet, float* __restrict__ y)
{
    const int r = blockIdx.x, tid = threadIdx.x;
    __shared__ float sh[16];
    const float* xr = x + (size_t)r * D_;
    float4 xv = *(const float4*)&xr[tid * 4];
    float s  = xv.x + xv.y + xv.z + xv.w;
    float ss = xv.x*xv.x + xv.y*xv.y + xv.z*xv.z + xv.w*xv.w;
    #pragma unroll
    for (int o = 16; o > 0; o >>= 1) {
        s  += __shfl_xor_sync(0xffffffffu, s,  o);
        ss += __shfl_xor_sync(0xffffffffu, ss, o);
    }
    if ((tid & 31) == 0) { sh[tid >> 5] = s; sh[8 + (tid >> 5)] = ss; }
    __syncthreads();
    float st = 0.f, sst = 0.f;
    #pragma unroll
    for (int w = 0; w < 8; w++) { st += sh[w]; sst += sh[8 + w]; }
    const float mu  = st * (1.0f / D_);
    const float var = sst * (1.0f / D_) - mu * mu;
    const float rs  = rsqrtf(var + 1e-5f);
    float4 gv = *(const float4*)&gam[tid * 4];
    float4 bv = *(const float4*)&bet[tid * 4];
    float4 o4;
    o4.x = (xv.x - mu) * rs * gv.x + bv.x;
    o4.y = (xv.y - mu) * rs * gv.y + bv.y;
    o4.z = (xv.z - mu) * rs * gv.z + bv.z;
    o4.w = (xv.w - mu) * rs * gv.w + bv.w;
    *(float4*)&y[(size_t)r * D_ + tid * 4] = o4;
}

// ===========================================================================
// Launch
// ===========================================================================
extern "C" void kernel_launch(void* const* d_in, const int* in_sizes, int n_in,
                              void* d_out, int out_size)
{
    const float* q_in = (const float*)d_in[0];
    const float* k_in = (const float*)d_in[1];
    const float* v_in = (const float*)d_in[2];
    const float* Wq   = (const float*)d_in[3];
    const float* Wq2  = (const float*)d_in[4];
    const float* Wk   = (const float*)d_in[5];
    const float* Wv   = (const float*)d_in[6];
    const float* Wo   = (const float*)d_in[7];
    const float* ln_g = (const float*)d_in[8];
    const float* ln_b = (const float*)d_in[9];
    const float* Er   = (const float*)d_in[10];
    (void)in_sizes; (void)n_in;

    float *pq, *pq2, *pk, *pvv, *patt, *px, *pfb;
    __nv_bfloat16 *ah, *al, *wh, *wl;
    cudaGetSymbolAddress((void**)&pq,   g_q);
    cudaGetSymbolAddress((void**)&pq2,  g_q2);
    cudaGetSymbolAddress((void**)&pk,   g_k);
    cudaGetSymbolAddress((void**)&pvv,  g_v);
    cudaGetSymbolAddress((void**)&patt, g_att);
    cudaGetSymbolAddress((void**)&px,   g_x);
    cudaGetSymbolAddress((void**)&pfb,  g_pfb);
    cudaGetSymbolAddress((void**)&ah,   g_ah);
    cudaGetSymbolAddress((void**)&al,   g_al);
    cudaGetSymbolAddress((void**)&wh,   g_wh);
    cudaGetSymbolAddress((void**)&wl,   g_wl);

    float* y_out = (float*)d_out;
    const long long ysz = (long long)B_ * L_ * D_;
    const long long psz = (long long)HB_ * L_ * L_;
    float* p_buf = ((long long)out_size >= ysz + psz) ? (y_out + ysz) : pfb;

    const int smem_sz = 2 * STAGE_BYTES;   // 81920 bytes
    cudaFuncSetAttribute(gemm_tc, cudaFuncAttributeMaxDynamicSharedMemorySize, smem_sz);

    const int M = B_ * L_;              // 4096
    const int nact = M * D_;            // 4,194,304
    const dim3 gsplit(nact / 1024);     // split_act grid
    const dim3 gwt(D_ / 32, D_ / 32);   // split_w_t grid
    const dim3 ggemm(D_ / 128, M / 128);

    // projections: q, q2 (share activation split of q_in)
    split_act<<<gsplit, 256>>>(q_in, ah, al, nact);
    split_w_t<<<gwt, 256>>>(Wq, wh, wl, D_, D_);
    gemm_tc<<<ggemm, 256, smem_sz>>>(ah, al, wh, wl, pq, nullptr, D_, D_);
    split_w_t<<<gwt, 256>>>(Wq2, wh, wl, D_, D_);
    gemm_tc<<<ggemm, 256, smem_sz>>>(ah, al, wh, wl, pq2, nullptr, D_, D_);
    // k
    split_act<<<gsplit, 256>>>(k_in, ah, al, nact);
    split_w_t<<<gwt, 256>>>(Wk, wh, wl, D_, D_);
    gemm_tc<<<ggemm, 256, smem_sz>>>(ah, al, wh, wl, pk, nullptr, D_, D_);
    // v
    split_act<<<gsplit, 256>>>(v_in, ah, al, nact);
    split_w_t<<<gwt, 256>>>(Wv, wh, wl, D_, D_);
    gemm_tc<<<ggemm, 256, smem_sz>>>(ah, al, wh, wl, pvv, nullptr, D_, D_);

    // attention middle (fp32 SIMT for now)
    score_kernel<<<dim3(16, 16, HB_), 256>>>(pq, pq2, pk, Er, p_buf);
    softmax_kernel<<<dim3(L_, HB_), 256>>>(p_buf);
    pv_kernel<<<dim3(16, HB_), 256>>>(p_buf, pvv, patt);

    // Wo GEMM with fused residual, then LN
    split_act<<<gsplit, 256>>>(patt, ah, al, nact);
    split_w_t<<<gwt, 256>>>(Wo, wh, wl, D_, D_);
    gemm_tc<<<ggemm, 256, smem_sz>>>(ah, al, wh, wl, px, q_in, D_, D_);
    ln_kernel<<<B_ * L_, 256>>>(px, ln_g, ln_b, y_out);
}

// round 4
// speedup vs baseline: 2.3600x; 1.4768x over previous
#include <cuda_runtime.h>
#include <cuda_bf16.h>
#include <cfloat>
#include <cstdint>

// Problem constants
#define B_  4
#define L_  1024
#define D_  1024
#define H_  16
#define HB_ 64   // H*B

// ===========================================================================
// Scratch (static __device__)
// ===========================================================================
__device__ float g_x  [B_ * L_ * D_];
__device__ float g_pfb[HB_ * L_ * L_];               // fallback p buffer
__device__ __nv_bfloat16 g_ah[B_ * L_ * D_];         // act / att split hi
__device__ __nv_bfloat16 g_al[B_ * L_ * D_];         // act / att split lo
__device__ __nv_bfloat16 g_wh[D_ * D_];              // weight^T split hi [N,K]
__device__ __nv_bfloat16 g_wl[D_ * D_];              // weight^T split lo [N,K]
__device__ __nv_bfloat16 g_qh [B_ * L_ * D_];
__device__ __nv_bfloat16 g_ql [B_ * L_ * D_];
__device__ __nv_bfloat16 g_q2h[B_ * L_ * D_];
__device__ __nv_bfloat16 g_q2l[B_ * L_ * D_];
__device__ __nv_bfloat16 g_kh [B_ * L_ * D_];
__device__ __nv_bfloat16 g_kl [B_ * L_ * D_];
__device__ __nv_bfloat16 g_vh [B_ * L_ * D_];
__device__ __nv_bfloat16 g_vl [B_ * L_ * D_];
__device__ __nv_bfloat16 g_eh [H_ * L_ * 64];
__device__ __nv_bfloat16 g_el [H_ * L_ * 64];

// ===========================================================================
// PTX helpers (base sm_103-legal)
// ===========================================================================
__device__ __forceinline__ uint32_t smem_u32(const void* p) {
    uint32_t a;
    asm("{ .reg .u64 t; cvta.to.shared.u64 t, %1; cvt.u32.u64 %0, t; }"
        : "=r"(a) : "l"(p));
    return a;
}
__device__ __forceinline__ void cpa16(uint32_t saddr, const void* g) {
    asm volatile("cp.async.cg.shared.global [%0], [%1], 16;" :: "r"(saddr), "l"(g));
}
__device__ __forceinline__ void cpa16z(uint32_t saddr, const void* g, int sz) {
    asm volatile("cp.async.cg.shared.global [%0], [%1], 16, %2;"
                 :: "r"(saddr), "l"(g), "r"(sz));
}
__device__ __forceinline__ void ldsm_x4(uint32_t* r, uint32_t addr) {
    asm volatile("ldmatrix.sync.aligned.m8n8.x4.shared.b16 {%0,%1,%2,%3}, [%4];"
                 : "=r"(r[0]), "=r"(r[1]), "=r"(r[2]), "=r"(r[3]) : "r"(addr));
}
__device__ __forceinline__ void ldsm_x4_t(uint32_t* r, uint32_t addr) {
    asm volatile("ldmatrix.sync.aligned.m8n8.x4.trans.shared.b16 {%0,%1,%2,%3}, [%4];"
                 : "=r"(r[0]), "=r"(r[1]), "=r"(r[2]), "=r"(r[3]) : "r"(addr));
}
__device__ __forceinline__ void mma16816(float* c, const uint32_t* a, const uint32_t* b) {
    asm volatile(
        "mma.sync.aligned.m16n8k16.row.col.f32.bf16.bf16.f32 "
        "{%0,%1,%2,%3}, {%4,%5,%6,%7}, {%8,%9}, {%0,%1,%2,%3};"
        : "+f"(c[0]), "+f"(c[1]), "+f"(c[2]), "+f"(c[3])
        : "r"(a[0]), "r"(a[1]), "r"(a[2]), "r"(a[3]), "r"(b[0]), "r"(b[1]));
}

// ===========================================================================
// fp32 -> bf16 hi/lo split (elementwise, n multiple of 4)
// ===========================================================================
__global__ __launch_bounds__(256)
void split_act(const float* __restrict__ x, __nv_bfloat16* __restrict__ hi,
               __nv_bfloat16* __restrict__ lo, int n)
{
    int i = (blockIdx.x * 256 + threadIdx.x) * 4;
    if (i >= n) return;
    float4 v = *(const float4*)&x[i];
    __nv_bfloat16 h0 = __float2bfloat16(v.x);
    __nv_bfloat16 h1 = __float2bfloat16(v.y);
    __nv_bfloat16 h2 = __float2bfloat16(v.z);
    __nv_bfloat16 h3 = __float2bfloat16(v.w);
    __nv_bfloat162 hp0; hp0.x = h0; hp0.y = h1;
    __nv_bfloat162 hp1; hp1.x = h2; hp1.y = h3;
    *(__nv_bfloat162*)&hi[i]     = hp0;
    *(__nv_bfloat162*)&hi[i + 2] = hp1;
    __nv_bfloat162 lp0, lp1;
    lp0.x = __float2bfloat16(v.x - __bfloat162float(h0));
    lp0.y = __float2bfloat16(v.y - __bfloat162float(h1));
    lp1.x = __float2bfloat16(v.z - __bfloat162float(h2));
    lp1.y = __float2bfloat16(v.w - __bfloat162float(h3));
    *(__nv_bfloat162*)&lo[i]     = lp0;
    *(__nv_bfloat162*)&lo[i + 2] = lp1;
}

// W[K,N] fp32 -> Wt[N,K] bf16 hi/lo (transpose + split)
__global__ __launch_bounds__(256)
void split_w_t(const float* __restrict__ W, __nv_bfloat16* __restrict__ th,
               __nv_bfloat16* __restrict__ tl, int Kd, int Nd)
{
    __shared__ float t[32][33];
    const int bx = blockIdx.x * 32;
    const int by = blockIdx.y * 32;
    const int tx = threadIdx.x & 31;
    const int ty = threadIdx.x >> 5;
    #pragma unroll
    for (int r = ty; r < 32; r += 8)
        t[r][tx] = W[(size_t)(by + r) * Nd + bx + tx];
    __syncthreads();
    #pragma unroll
    for (int r = ty; r < 32; r += 8) {
        float v = t[tx][r];
        __nv_bfloat16 h = __float2bfloat16(v);
        th[(size_t)(bx + r) * Kd + by + tx] = h;
        tl[(size_t)(bx + r) * Kd + by + tx] = __float2bfloat16(v - __bfloat162float(h));
    }
}

// ===========================================================================
// HMMA split-bf16 GEMM: C = (Ah+Al)[M,K] @ (Bh+Bl)[N,K]^T
// Output: fp32 C (+R residual) OR bf16 hi/lo pair (Oh/Ol).
// ===========================================================================
#define TSTRIDE 40
#define TILE_BYTES (128 * TSTRIDE * 2)
#define STAGE_BYTES (4 * TILE_BYTES)

__global__ __launch_bounds__(256)
void gemm_tc(const __nv_bfloat16* __restrict__ Ah, const __nv_bfloat16* __restrict__ Al,
             const __nv_bfloat16* __restrict__ Bh, const __nv_bfloat16* __restrict__ Bl,
             float* __restrict__ C, const float* __restrict__ R,
             __nv_bfloat16* __restrict__ Oh, __nv_bfloat16* __restrict__ Ol,
             int K, int N)
{
    extern __shared__ __align__(16) char smem[];
    const uint32_t sb0 = smem_u32(smem);
    const int tid  = threadIdx.x;
    const int wid  = tid >> 5;
    const int lane = tid & 31;
    const int m0 = blockIdx.y * 128;
    const int n0 = blockIdx.x * 128;
    const int wm = (wid & 3) * 32;
    const int wn = (wid >> 2) * 64;

    const __nv_bfloat16* gT[4] = {
        Ah + (size_t)m0 * K, Al + (size_t)m0 * K,
        Bh + (size_t)n0 * K, Bl + (size_t)n0 * K };

    auto load_chunk = [&](int c, int st) {
        const uint32_t sb = sb0 + st * STAGE_BYTES;
        const int k0 = c * 32;
        #pragma unroll
        for (int t = 0; t < 4; t++) {
            const __nv_bfloat16* g = gT[t] + k0;
            const uint32_t tb = sb + t * TILE_BYTES;
            #pragma unroll
            for (int it = 0; it < 2; it++) {
                int o   = tid + it * 256;
                int row = o >> 2, c16 = o & 3;
                cpa16(tb + row * (TSTRIDE * 2) + c16 * 16,
                      g + (size_t)row * K + c16 * 8);
            }
        }
        asm volatile("cp.async.commit_group;" ::: "memory");
    };

    float acc[2][8][4];
    #pragma unroll
    for (int i = 0; i < 2; i++)
        #pragma unroll
        for (int j = 0; j < 8; j++)
            #pragma unroll
            for (int q = 0; q < 4; q++) acc[i][j][q] = 0.f;

    const int arow = lane & 15;
    const int acolq = (lane >> 4) * 8;
    const int nrow = ((lane >> 4) * 8) + (lane & 7);
    const int bcolq = ((lane >> 3) & 1) * 8;

    const int NC = K / 32;
    load_chunk(0, 0);

    for (int c = 0; c < NC; ++c) {
        const int st = c & 1;
        if (c + 1 < NC) {
            load_chunk(c + 1, st ^ 1);
            asm volatile("cp.async.wait_group 1;" ::: "memory");
        } else {
            asm volatile("cp.async.wait_group 0;" ::: "memory");
        }
        __syncthreads();

        const uint32_t sb  = sb0 + st * STAGE_BYTES;
        const uint32_t sAh = sb;
        const uint32_t sAl = sb + TILE_BYTES;
        const uint32_t sBh = sb + 2 * TILE_BYTES;
        const uint32_t sBl = sb + 3 * TILE_BYTES;

        #pragma unroll
        for (int k16 = 0; k16 < 32; k16 += 16) {
            uint32_t ah[2][4], al[2][4], bh[4][4], bl[4][4];
            #pragma unroll
            for (int mt = 0; mt < 2; mt++) {
                uint32_t off = ((wm + mt * 16 + arow) * TSTRIDE + k16 + acolq) * 2;
                ldsm_x4(ah[mt], sAh + off);
                ldsm_x4(al[mt], sAl + off);
            }
            #pragma unroll
            for (int p = 0; p < 4; p++) {
                uint32_t off = ((wn + p * 16 + nrow) * TSTRIDE + k16 + bcolq) * 2;
                ldsm_x4(bh[p], sBh + off);
                ldsm_x4(bl[p], sBl + off);
            }
            #pragma unroll
            for (int mt = 0; mt < 2; mt++)
                #pragma unroll
                for (int nt = 0; nt < 8; nt++) {
                    const uint32_t* bhf = &bh[nt >> 1][(nt & 1) * 2];
                    const uint32_t* blf = &bl[nt >> 1][(nt & 1) * 2];
                    mma16816(acc[mt][nt], ah[mt], bhf);
                    mma16816(acc[mt][nt], ah[mt], blf);
                    mma16816(acc[mt][nt], al[mt], bhf);
                }
        }
        __syncthreads();
    }

    #pragma unroll
    for (int mt = 0; mt < 2; mt++) {
        const int m = m0 + wm + mt * 16 + (lane >> 2);
        #pragma unroll
        for (int nt = 0; nt < 8; nt++) {
            const int n = n0 + wn + nt * 8 + (lane & 3) * 2;
            if (Oh) {
                #pragma unroll
                for (int rr = 0; rr < 2; rr++) {
                    const size_t idx = (size_t)(m + rr * 8) * N + n;
                    float a0 = acc[mt][nt][rr * 2], a1 = acc[mt][nt][rr * 2 + 1];
                    __nv_bfloat162 hh, ll;
                    hh.x = __float2bfloat16(a0);
                    hh.y = __float2bfloat16(a1);
                    ll.x = __float2bfloat16(a0 - __bfloat162float(hh.x));
                    ll.y = __float2bfloat16(a1 - __bfloat162float(hh.y));
                    *(__nv_bfloat162*)&Oh[idx] = hh;
                    *(__nv_bfloat162*)&Ol[idx] = ll;
                }
            } else {
                float2 o0 = make_float2(acc[mt][nt][0], acc[mt][nt][1]);
                float2 o1 = make_float2(acc[mt][nt][2], acc[mt][nt][3]);
                if (R) {
                    const float2 r0 = *(const float2*)&R[(size_t)m * N + n];
                    const float2 r1 = *(const float2*)&R[(size_t)(m + 8) * N + n];
                    o0.x += r0.x; o0.y += r0.y;
                    o1.x += r1.x; o1.y += r1.y;
                }
                *(float2*)&C[(size_t)m * N + n] = o0;
                *(float2*)&C[(size_t)(m + 8) * N + n] = o1;
            }
        }
    }
}

// ===========================================================================
// HMMA score kernel: S[i,j] = (q_i.k_j + q2_i.Er[L-1-(i-j)]) / 8, j <= i tiles
// 64x64 tiles, 128 threads (4 warps x 16 rows). qk HMMA + rel band-HMMA
// with per-warp smem gather for the skew.
// ===========================================================================
#define SC_SQH 0
#define SC_SQL 8192
#define SC_S2H 16384
#define SC_S2L 24576
#define SC_SKH 32768
#define SC_SKL 40960
#define SC_SEH 49152
#define SC_SEL 65536
#define SC_SR  81920
#define SC_SMEM (81920 + 4 * 5632)   // 104448

__global__ __launch_bounds__(128)
void score_tc(const __nv_bfloat16* __restrict__ qh, const __nv_bfloat16* __restrict__ ql,
              const __nv_bfloat16* __restrict__ q2h, const __nv_bfloat16* __restrict__ q2l,
              const __nv_bfloat16* __restrict__ kh, const __nv_bfloat16* __restrict__ kl,
              const __nv_bfloat16* __restrict__ eh, const __nv_bfloat16* __restrict__ el,
              float* __restrict__ p)
{
    const int tj = blockIdx.x, ti = blockIdx.y, z = blockIdx.z;
    if (tj > ti) return;
    const int i0 = ti * 64, j0 = tj * 64;
    const int h = z >> 2, b = z & 3;
    const int rbase = L_ - 64 - i0 + j0;

    extern __shared__ __align__(16) char smem[];
    const uint32_t sb = smem_u32(smem);
    const int tid = threadIdx.x;
    const int lane = tid & 31, w = tid >> 5;

    // ---- load 64-row tiles (q/q2/k: row stride D_, 64 cols) ----
    auto load64 = [&](uint32_t st, const __nv_bfloat16* g) {
        #pragma unroll
        for (int t = 0; t < 4; t++) {
            int cid = tid + t * 128;          // 0..511
            int row = cid >> 3, c = cid & 7;
            cpa16(sb + st + row * 128 + ((c ^ (row & 7)) * 16),
                  g + (size_t)row * D_ + c * 8);
        }
    };
    const size_t qoff = (size_t)(b * L_ + i0) * D_ + h * 64;
    const size_t koff = (size_t)(b * L_ + j0) * D_ + h * 64;
    load64(SC_SQH, qh  + qoff);
    load64(SC_SQL, ql  + qoff);
    load64(SC_S2H, q2h + qoff);
    load64(SC_S2L, q2l + qoff);
    load64(SC_SKH, kh  + koff);
    load64(SC_SKL, kl  + koff);
    // Er band: 128 rows, stride 64, zero-fill rows >= L
    {
        const __nv_bfloat16* ehp = eh + (size_t)h * L_ * 64;
        const __nv_bfloat16* elp = el + (size_t)h * L_ * 64;
        #pragma unroll
        for (int t = 0; t < 8; t++) {
            int cid = tid + t * 128;          // 0..1023
            int row = cid >> 3, c = cid & 7;
            int r = rbase + row;
            int sz = (r < L_) ? 16 : 0;
            int rc = (r < L_) ? r : 0;
            uint32_t so = row * 128 + ((c ^ (row & 7)) * 16);
            cpa16z(sb + SC_SEH + so, ehp + (size_t)rc * 64 + c * 8, sz);
            cpa16z(sb + SC_SEL + so, elp + (size_t)rc * 64 + c * 8, sz);
        }
    }
    asm volatile("cp.async.commit_group;" ::: "memory");
    asm volatile("cp.async.wait_group 0;" ::: "memory");
    __syncthreads();

    float aqk[8][4], arl[10][4];
    #pragma unroll
    for (int i = 0; i < 8; i++)
        #pragma unroll
        for (int q = 0; q < 4; q++) aqk[i][q] = 0.f;
    #pragma unroll
    for (int i = 0; i < 10; i++)
        #pragma unroll
        for (int q = 0; q < 4; q++) arl[i][q] = 0.f;

    const int t0w = 48 - 16 * w;

    auto ldA = [&](uint32_t st, int k16, uint32_t* r) {
        int row = 16 * w + (lane & 15);
        int c = (k16 >> 3) + (lane >> 4);
        ldsm_x4(r, sb + st + row * 128 + ((c ^ (row & 7)) * 16));
    };
    auto ldB = [&](uint32_t st, int nrow0, int k16, uint32_t* r) {
        int row = nrow0 + (lane >> 4) * 8 + (lane & 7);
        int c = (k16 >> 3) + ((lane >> 3) & 1);
        ldsm_x4(r, sb + st + row * 128 + ((c ^ (row & 7)) * 16));
    };

    #pragma unroll
    for (int k16 = 0; k16 < 64; k16 += 16) {
        uint32_t Aqh[4], Aql[4], A2h[4], A2l[4];
        ldA(SC_SQH, k16, Aqh);
        ldA(SC_SQL, k16, Aql);
        ldA(SC_S2H, k16, A2h);
        ldA(SC_S2L, k16, A2l);
        #pragma unroll
        for (int pg = 0; pg < 4; pg++) {
            uint32_t Bh[4], Bl[4];
            ldB(SC_SKH, pg * 16, k16, Bh);
            ldB(SC_SKL, pg * 16, k16, Bl);
            mma16816(aqk[2 * pg],     Aqh, Bh);
            mma16816(aqk[2 * pg + 1], Aqh, Bh + 2);
            mma16816(aqk[2 * pg],     Aqh, Bl);
            mma16816(aqk[2 * pg + 1], Aqh, Bl + 2);
            mma16816(aqk[2 * pg],     Aql, Bh);
            mma16816(aqk[2 * pg + 1], Aql, Bh + 2);
        }
        #pragma unroll
        for (int pg = 0; pg < 5; pg++) {
            uint32_t Bh[4], Bl[4];
            ldB(SC_SEH, t0w + pg * 16, k16, Bh);
            ldB(SC_SEL, t0w + pg * 16, k16, Bl);
            mma16816(arl[2 * pg],     A2h, Bh);
            mma16816(arl[2 * pg + 1], A2h, Bh + 2);
            mma16816(arl[2 * pg],     A2h, Bl);
            mma16816(arl[2 * pg + 1], A2h, Bl + 2);
            mma16816(arl[2 * pg],     A2l, Bh);
            mma16816(arl[2 * pg + 1], A2l, Bh + 2);
        }
    }

    // ---- skew gather (per-warp private) ----
    float* Rs = (float*)(smem + SC_SR + w * 5632);   // 16 x 88 fp32
    const int r0 = lane >> 2, cb = (lane & 3) * 2;
    #pragma unroll
    for (int nt = 0; nt < 10; nt++) {
        int tb = nt * 8 + cb;
        Rs[r0 * 88 + tb]           = arl[nt][0];
        Rs[r0 * 88 + tb + 1]       = arl[nt][1];
        Rs[(r0 + 8) * 88 + tb]     = arl[nt][2];
        Rs[(r0 + 8) * 88 + tb + 1] = arl[nt][3];
    }
    __syncwarp();

    #pragma unroll
    for (int nt = 0; nt < 8; nt++) {
        int jj = nt * 8 + cb;
        float2 o0, o1;
        o0.x = (aqk[nt][0] + Rs[r0 * 88 + 15 + jj - r0]) * 0.125f;
        o0.y = (aqk[nt][1] + Rs[r0 * 88 + 16 + jj - r0]) * 0.125f;
        o1.x = (aqk[nt][2] + Rs[(r0 + 8) * 88 + 7 + jj - r0]) * 0.125f;
        o1.y = (aqk[nt][3] + Rs[(r0 + 8) * 88 + 8 + jj - r0]) * 0.125f;
        size_t base = ((size_t)z * L_ + i0 + 16 * w + r0) * L_ + j0 + jj;
        *(float2*)&p[base]          = o0;
        *(float2*)&p[base + 8 * L_] = o1;
    }
}

// ===========================================================================
// Single-pass row softmax: read row once into registers, write once.
// Forces -inf for j > i (also initializes the never-written upper triangle).
// ===========================================================================
__global__ __launch_bounds__(256)
void softmax1p(float* __restrict__ p)
{
    const int i = blockIdx.x, z = blockIdx.y, tid = threadIdx.x;
    float* row = p + ((size_t)z * L_ + i) * L_;
    __shared__ float sh[8];

    const int j0 = tid * 4;
    float4 x = *(const float4*)&row[j0];
    if (j0 + 0 > i) x.x = -FLT_MAX;
    if (j0 + 1 > i) x.y = -FLT_MAX;
    if (j0 + 2 > i) x.z = -FLT_MAX;
    if (j0 + 3 > i) x.w = -FLT_MAX;

    float m = fmaxf(fmaxf(x.x, x.y), fmaxf(x.z, x.w));
    #pragma unroll
    for (int o = 16; o > 0; o >>= 1) m = fmaxf(m, __shfl_xor_sync(0xffffffffu, m, o));
    if ((tid & 31) == 0) sh[tid >> 5] = m;
    __syncthreads();
    float mt = -FLT_MAX;
    #pragma unroll
    for (int wv = 0; wv < 8; wv++) mt = fmaxf(mt, sh[wv]);
    __syncthreads();

    float4 e;
    e.x = __expf(x.x - mt);
    e.y = __expf(x.y - mt);
    e.z = __expf(x.z - mt);
    e.w = __expf(x.w - mt);
    float s = e.x + e.y + e.z + e.w;
    #pragma unroll
    for (int o = 16; o > 0; o >>= 1) s += __shfl_xor_sync(0xffffffffu, s, o);
    if ((tid & 31) == 0) sh[tid >> 5] = s;
    __syncthreads();
    float st = 0.f;
    #pragma unroll
    for (int wv = 0; wv < 8; wv++) st += sh[wv];
    const float inv = 1.0f / st;

    e.x *= inv; e.y *= inv; e.z *= inv; e.w *= inv;
    *(float4*)&row[j0] = e;
}

// ===========================================================================
// HMMA pv: out[i,d] = sum_{j<=i} p[i,j] v[j,d]; writes att bf16 hi/lo directly.
// 128 threads (4 warps x 16 rows), j-chunks of 32, double-buffered v.
// ===========================================================================
__global__ __launch_bounds__(128)
void pv_tc(const float* __restrict__ p,
           const __nv_bfloat16* __restrict__ vh, const __nv_bfloat16* __restrict__ vl,
           __nv_bfloat16* __restrict__ oh, __nv_bfloat16* __restrict__ ol)
{
    const int ti = blockIdx.x, z = blockIdx.y;
    const int i0 = ti * 64;
    const int h = z >> 2, b = z & 3;
    const int tid = threadIdx.x;
    const int lane = tid & 31, w = tid >> 5;

    __shared__ __align__(128) char sv[2][2][4096];   // [buf][h/l][32 rows x 128B]
    __shared__ __align__(128) char sp[4][2][1280];   // [warp][h/l][16 rows x 80B]
    const uint32_t svb = smem_u32(&sv[0][0][0]);
    const uint32_t spw = smem_u32(&sp[w][0][0]);

    auto loadV = [&](int kj, int bi) {
        #pragma unroll
        for (int t = 0; t < 4; t++) {
            int cid = tid + t * 128;                 // 0..511
            int sel = cid >> 8, rid = (cid >> 3) & 31, c = cid & 7;
            const __nv_bfloat16* g = (sel ? vl : vh)
                + ((size_t)(b * L_ + kj + rid) * D_ + h * 64 + c * 8);
            cpa16(svb + bi * 8192 + sel * 4096 + rid * 128 + ((c ^ (rid & 7)) * 16), g);
        }
        asm volatile("cp.async.commit_group;" ::: "memory");
    };

    float acc[8][4];
    #pragma unroll
    for (int i = 0; i < 8; i++)
        #pragma unroll
        for (int q = 0; q < 4; q++) acc[i][q] = 0.f;

    const int nch = (i0 + 64) >> 5;
    loadV(0, 0);

    for (int c = 0; c < nch; c++) {
        const int bi = c & 1;
        __syncthreads();                 // prior iter's reads of buffer bi^1 done
        if (c + 1 < nch) loadV((c + 1) * 32, bi ^ 1);

        // per-warp p conversion: rows 16w..16w+15, cols kj..kj+31
        {
            const int row = lane >> 1, chalf = lane & 1;
            const float* gp = p + ((size_t)z * L_ + i0 + 16 * w + row) * L_
                                + c * 32 + chalf * 16;
            uint32_t* ph = (uint32_t*)(&sp[w][0][0] + row * 80 + chalf * 32);
            uint32_t* pl = (uint32_t*)(&sp[w][1][0] + row * 80 + chalf * 32);
            #pragma unroll
            for (int q = 0; q < 4; q++) {
                float4 v = *(const float4*)(gp + q * 4);
                __nv_bfloat162 h0, h1, l0, l1;
                h0.x = __float2bfloat16(v.x); h0.y = __float2bfloat16(v.y);
                h1.x = __float2bfloat16(v.z); h1.y = __float2bfloat16(v.w);
                l0.x = __float2bfloat16(v.x - __bfloat162float(h0.x));
                l0.y = __float2bfloat16(v.y - __bfloat162float(h0.y));
                l1.x = __float2bfloat16(v.z - __bfloat162float(h1.x));
                l1.y = __float2bfloat16(v.w - __bfloat162float(h1.y));
                ph[q * 2]     = *(uint32_t*)&h0;
                ph[q * 2 + 1] = *(uint32_t*)&h1;
                pl[q * 2]     = *(uint32_t*)&l0;
                pl[q * 2 + 1] = *(uint32_t*)&l1;
            }
        }
        __syncwarp();
        if (c + 1 < nch) asm volatile("cp.async.wait_group 1;" ::: "memory");
        else             asm volatile("cp.async.wait_group 0;" ::: "memory");
        __syncthreads();

        #pragma unroll
        for (int k16 = 0; k16 < 32; k16 += 16) {
            uint32_t Aph[4], Apl[4];
            {
                int arow = lane & 15;
                int ac = (k16 >> 3) + (lane >> 4);
                ldsm_x4(Aph, spw + arow * 80 + ac * 16);
                ldsm_x4(Apl, spw + 1280 + arow * 80 + ac * 16);
            }
            #pragma unroll
            for (int p4 = 0; p4 < 4; p4++) {
                uint32_t Bh[4], Bl[4];
                int krow = k16 + ((lane >> 3) & 1) * 8 + (lane & 7);
                int cc = p4 * 2 + (lane >> 4);
                uint32_t off = krow * 128 + ((cc ^ (krow & 7)) * 16);
                ldsm_x4_t(Bh, svb + bi * 8192 + off);
                ldsm_x4_t(Bl, svb + bi * 8192 + 4096 + off);
                mma16816(acc[2 * p4],     Aph, Bh);
                mma16816(acc[2 * p4 + 1], Aph, Bh + 2);
                mma16816(acc[2 * p4],     Aph, Bl);
                mma16816(acc[2 * p4 + 1], Aph, Bl + 2);
                mma16816(acc[2 * p4],     Apl, Bh);
                mma16816(acc[2 * p4 + 1], Apl, Bh + 2);
            }
        }
    }

    // epilogue: att -> bf16 hi/lo
    const int r0 = lane >> 2, cb = (lane & 3) * 2;
    #pragma unroll
    for (int nt = 0; nt < 8; nt++) {
        const int d = nt * 8 + cb;
        #pragma unroll
        for (int rr = 0; rr < 2; rr++) {
            const int i = i0 + 16 * w + r0 + rr * 8;
            const size_t idx = (size_t)(b * L_ + i) * D_ + h * 64 + d;
            float a0 = acc[nt][rr * 2], a1 = acc[nt][rr * 2 + 1];
            __nv_bfloat162 hh, ll;
            hh.x = __float2bfloat16(a0);
            hh.y = __float2bfloat16(a1);
            ll.x = __float2bfloat16(a0 - __bfloat162float(hh.x));
            ll.y = __float2bfloat16(a1 - __bfloat162float(hh.y));
            *(__nv_bfloat162*)&oh[idx] = hh;
            *(__nv_bfloat162*)&ol[idx] = ll;
        }
    }
}

// ===========================================================================
// LayerNorm
// ===========================================================================
__global__ __launch_bounds__(256)
void ln_kernel(const float* __restrict__ x, const float* __restrict__ gam,
               const float* __restrict__ bet, float* __restrict__ y)
{
    const int r = blockIdx.x, tid = threadIdx.x;
    __shared__ float sh[16];
    const float* xr = x + (size_t)r * D_;
    float4 xv = *(const float4*)&xr[tid * 4];
    float s  = xv.x + xv.y + xv.z + xv.w;
    float ss = xv.x*xv.x + xv.y*xv.y + xv.z*xv.z + xv.w*xv.w;
    #pragma unroll
    for (int o = 16; o > 0; o >>= 1) {
        s  += __shfl_xor_sync(0xffffffffu, s,  o);
        ss += __shfl_xor_sync(0xffffffffu, ss, o);
    }
    if ((tid & 31) == 0) { sh[tid >> 5] = s; sh[8 + (tid >> 5)] = ss; }
    __syncthreads();
    float st = 0.f, sst = 0.f;
    #pragma unroll
    for (int wv = 0; wv < 8; wv++) { st += sh[wv]; sst += sh[8 + wv]; }
    const float mu  = st * (1.0f / D_);
    const float var = sst * (1.0f / D_) - mu * mu;
    const float rs  = rsqrtf(var + 1e-5f);
    float4 gv = *(const float4*)&gam[tid * 4];
    float4 bv = *(const float4*)&bet[tid * 4];
    float4 o4;
    o4.x = (xv.x - mu) * rs * gv.x + bv.x;
    o4.y = (xv.y - mu) * rs * gv.y + bv.y;
    o4.z = (xv.z - mu) * rs * gv.z + bv.z;
    o4.w = (xv.w - mu) * rs * gv.w + bv.w;
    *(float4*)&y[(size_t)r * D_ + tid * 4] = o4;
}

// ===========================================================================
// Launch
// ===========================================================================
extern "C" void kernel_launch(void* const* d_in, const int* in_sizes, int n_in,
                              void* d_out, int out_size)
{
    const float* q_in = (const float*)d_in[0];
    const float* k_in = (const float*)d_in[1];
    const float* v_in = (const float*)d_in[2];
    const float* Wq   = (const float*)d_in[3];
    const float* Wq2  = (const float*)d_in[4];
    const float* Wk   = (const float*)d_in[5];
    const float* Wv   = (const float*)d_in[6];
    const float* Wo   = (const float*)d_in[7];
    const float* ln_g = (const float*)d_in[8];
    const float* ln_b = (const float*)d_in[9];
    const float* Er   = (const float*)d_in[10];
    (void)in_sizes; (void)n_in;

    float *px, *pfb;
    __nv_bfloat16 *ah, *al, *wh, *wl, *qh, *ql, *q2h, *q2l, *kh, *kl, *vh, *vl, *eh, *el;
    cudaGetSymbolAddress((void**)&px,  g_x);
    cudaGetSymbolAddress((void**)&pfb, g_pfb);
    cudaGetSymbolAddress((void**)&ah,  g_ah);
    cudaGetSymbolAddress((void**)&al,  g_al);
    cudaGetSymbolAddress((void**)&wh,  g_wh);
    cudaGetSymbolAddress((void**)&wl,  g_wl);
    cudaGetSymbolAddress((void**)&qh,  g_qh);
    cudaGetSymbolAddress((void**)&ql,  g_ql);
    cudaGetSymbolAddress((void**)&q2h, g_q2h);
    cudaGetSymbolAddress((void**)&q2l, g_q2l);
    cudaGetSymbolAddress((void**)&kh,  g_kh);
    cudaGetSymbolAddress((void**)&kl,  g_kl);
    cudaGetSymbolAddress((void**)&vh,  g_vh);
    cudaGetSymbolAddress((void**)&vl,  g_vl);
    cudaGetSymbolAddress((void**)&eh,  g_eh);
    cudaGetSymbolAddress((void**)&el,  g_el);

    float* y_out = (float*)d_out;
    const long long ysz = (long long)B_ * L_ * D_;
    const long long psz = (long long)HB_ * L_ * L_;
    float* p_buf = ((long long)out_size >= ysz + psz) ? (y_out + ysz) : pfb;

    const int gsmem = 2 * STAGE_BYTES;
    cudaFuncSetAttribute(gemm_tc, cudaFuncAttributeMaxDynamicSharedMemorySize, gsmem);
    cudaFuncSetAttribute(score_tc, cudaFuncAttributeMaxDynamicSharedMemorySize, SC_SMEM);

    const int M = B_ * L_;
    const int nact = M * D_;
    const dim3 gsplit(nact / 1024);
    const dim3 gwt(D_ / 32, D_ / 32);
    const dim3 ggemm(D_ / 128, M / 128);

    // projections -> bf16 hi/lo outputs
    split_act<<<gsplit, 256>>>(q_in, ah, al, nact);
    split_w_t<<<gwt, 256>>>(Wq, wh, wl, D_, D_);
    gemm_tc<<<ggemm, 256, gsmem>>>(ah, al, wh, wl, nullptr, nullptr, qh, ql, D_, D_);
    split_w_t<<<gwt, 256>>>(Wq2, wh, wl, D_, D_);
    gemm_tc<<<ggemm, 256, gsmem>>>(ah, al, wh, wl, nullptr, nullptr, q2h, q2l, D_, D_);
    split_act<<<gsplit, 256>>>(k_in, ah, al, nact);
    split_w_t<<<gwt, 256>>>(Wk, wh, wl, D_, D_);
    gemm_tc<<<ggemm, 256, gsmem>>>(ah, al, wh, wl, nullptr, nullptr, kh, kl, D_, D_);
    split_act<<<gsplit, 256>>>(v_in, ah, al, nact);
    split_w_t<<<gwt, 256>>>(Wv, wh, wl, D_, D_);
    gemm_tc<<<ggemm, 256, gsmem>>>(ah, al, wh, wl, nullptr, nullptr, vh, vl, D_, D_);

    // Er split
    split_act<<<dim3(H_ * L_ * 64 / 1024), 256>>>(Er, eh, el, H_ * L_ * 64);

    // attention middle (all HMMA)
    score_tc<<<dim3(16, 16, HB_), 128, SC_SMEM>>>(qh, ql, q2h, q2l, kh, kl, eh, el, p_buf);
    softmax1p<<<dim3(L_, HB_), 256>>>(p_buf);
    pv_tc<<<dim3(16, HB_), 128>>>(p_buf, vh, vl, ah, al);

    // Wo GEMM (fp32 out + residual), then LN
    split_w_t<<<gwt, 256>>>(Wo, wh, wl, D_, D_);
    gemm_tc<<<ggemm, 256, gsmem>>>(ah, al, wh, wl, px, q_in, nullptr, nullptr, D_, D_);
    ln_kernel<<<B_ * L_, 256>>>(px, ln_g, ln_b, y_out);
}